// round 7
// baseline (speedup 1.0000x reference)
#include <cuda_runtime.h>
#include <cuda_fp16.h>
#include <cuda_fp8.h>
#include <cstdint>

// ---------------- Problem constants (fixed-shape bench) ----------------
#define T_MAX   8192
#define K_DIM   4096
#define O_DIM   4096
#define FP8_MAX 448.0f

// ---------------- GEMM tiling (fp8 mma.sync m16n8k32, f16 accum) ----------------
#define BM 128
#define BN 128
#define BK 128                   // fp8 elements per k-chunk == one weight-scale k-block
#define STAGES 5
#define KTOT   (K_DIM / BK)      // 32 k-blocks
#define ROWB   144               // 128 B data + 16 B pad per smem row
#define A_STAGE_BYTES (BM * ROWB)        // 18432
#define B_STAGE_BYTES (BN * ROWB)        // 18432
#define STAGE_BYTES   (A_STAGE_BYTES + B_STAGE_BYTES)
#define SMEM_BYTES    (STAGES * STAGE_BYTES)   // 184320 <= 227KB

// ---------------- Scratch (static device globals; no allocation) ----------------
__device__ __align__(1024) uint8_t g_xq[(size_t)T_MAX * K_DIM];   // 32 MB fp8 (x/xs/32)
__device__ __align__(1024) uint8_t g_wq[(size_t)O_DIM * K_DIM];   // 16 MB fp8
__device__ float g_xs[T_MAX];

// ---------------- PTX helpers (base ISA only) ----------------
__device__ __forceinline__ uint32_t smem_u32(const void* p) {
    uint32_t a;
    asm("{ .reg .u64 t; cvta.to.shared.u64 t, %1; cvt.u32.u64 %0, t; }" : "=r"(a) : "l"(p));
    return a;
}

#define CP_ASYNC_CG16(saddr, gptr) \
    asm volatile("cp.async.cg.shared.global [%0], [%1], 16;" :: "r"(saddr), "l"(gptr) : "memory")
#define CP_COMMIT() asm volatile("cp.async.commit_group;" ::: "memory")
#define CP_WAIT(n)  asm volatile("cp.async.wait_group %0;" :: "n"(n) : "memory")

#define LDSM_X4(r, addr) \
    asm volatile("ldmatrix.sync.aligned.m8n8.x4.shared.b16 {%0,%1,%2,%3}, [%4];" \
        : "=r"((r)[0]), "=r"((r)[1]), "=r"((r)[2]), "=r"((r)[3]) : "r"(addr))

// dc += a*b  (e4m3 x e4m3 -> f16 accum), m16n8k32; dc = 2 regs of f16x2
#define MMA_FP8_H(dc, a, b0, b1) \
    asm volatile("mma.sync.aligned.m16n8k32.row.col.f16.e4m3.e4m3.f16 " \
        "{%0,%1}, {%2,%3,%4,%5}, {%6,%7}, {%0,%1};" \
        : "+r"((dc)[0]), "+r"((dc)[1]) \
        : "r"((a)[0]), "r"((a)[1]), "r"((a)[2]), "r"((a)[3]), "r"(b0), "r"(b1))

// ---------------- Kernel 1: per-token amax + quantize x/32 -> e4m3 bytes ----------------
__device__ __forceinline__ uint16_t f2_to_fp8x2(float a, float b) {
    return __nv_cvt_float2_to_fp8x2(make_float2(a, b), __NV_SATFINITE, __NV_E4M3);
}

__global__ void __launch_bounds__(256) quant_x_kernel(
    const float* __restrict__ x, uint8_t* __restrict__ xq, float* __restrict__ xs)
{
    int row = blockIdx.x;
    int tid = threadIdx.x;
    const float4* xr = reinterpret_cast<const float4*>(x + (size_t)row * K_DIM);
    float4 v[4];
    float am = 0.0f;
#pragma unroll
    for (int j = 0; j < 4; j++) {
        v[j] = xr[tid * 4 + j];            // 16 consecutive floats per thread
        am = fmaxf(am, fmaxf(fmaxf(fabsf(v[j].x), fabsf(v[j].y)),
                             fmaxf(fabsf(v[j].z), fabsf(v[j].w))));
    }
#pragma unroll
    for (int o = 16; o > 0; o >>= 1)
        am = fmaxf(am, __shfl_xor_sync(0xffffffffu, am, o));
    __shared__ float red[8];
    if ((tid & 31) == 0) red[tid >> 5] = am;
    __syncthreads();
    float m = red[0];
#pragma unroll
    for (int i = 1; i < 8; i++) m = fmaxf(m, red[i]);
    m = fmaxf(m, 1e-12f);
    float scale = m / FP8_MAX;
    if (tid == 0) xs[row] = scale;
    float rs = 1.0f / (scale * 32.0f);     // store x_fp8/32 (exact /32; folded back later)
    uint32_t pk[4];
#pragma unroll
    for (int j = 0; j < 4; j++) {
        uint32_t lo = f2_to_fp8x2(v[j].x * rs, v[j].y * rs);
        uint32_t hi = f2_to_fp8x2(v[j].z * rs, v[j].w * rs);
        pk[j] = lo | (hi << 16);
    }
    *reinterpret_cast<uint4*>(xq + (size_t)row * K_DIM + tid * 16) =
        make_uint4(pk[0], pk[1], pk[2], pk[3]);
}

// ---------------- Kernel 2: pack weight (already e4m3-valued f32) -> e4m3 bytes ----------------
__global__ void __launch_bounds__(256) pack_w_kernel(
    const float* __restrict__ w, uint8_t* __restrict__ wq)
{
    size_t idx = ((size_t)blockIdx.x * blockDim.x + threadIdx.x) * 4;
    float4 v = *reinterpret_cast<const float4*>(w + idx);
    uint32_t lo = f2_to_fp8x2(v.x, v.y);
    uint32_t hi = f2_to_fp8x2(v.z, v.w);
    *reinterpret_cast<uint32_t*>(wq + idx) = lo | (hi << 16);
}

// ---------------- Kernel 3: fp8 mma (f16 accum) GEMM, 128x128x128, 5-stage cp.async ----------------
// Per 128-k block: chain 4 f16-accum MMAs, promote once to f32 with ws[oblk,kb]*32.
__global__ void __launch_bounds__(256, 1) gemm_kernel(
    float* __restrict__ out, const float* __restrict__ xs,
    const float* __restrict__ ws,            // [O/128, K/128]
    const uint8_t* __restrict__ A,           // [T, K] e4m3 (x/32)
    const uint8_t* __restrict__ B,           // [O, K] e4m3
    int ntiles_n)
{
    extern __shared__ char smem[];
    const uint32_t smA = smem_u32(smem);
    const uint32_t smB = smA + STAGES * A_STAGE_BYTES;

    const int tid  = threadIdx.x;
    const int lane = tid & 31;
    const int wid  = tid >> 5;
    const int wm   = wid & 1;    // 2 warp rows (64 M each)
    const int wn   = wid >> 1;   // 4 warp cols (32 N each)

    const int ntile = blockIdx.x % ntiles_n;
    const int mtile = blockIdx.x / ntiles_n;

    const uint8_t* gA = A + (size_t)(mtile * BM) * K_DIM;
    const uint8_t* gB = B + (size_t)(ntile * BN) * K_DIM;
    const float*   wsrow = ws + (size_t)ntile * KTOT;    // one o-block per CTA

    float macc[4][4][4];
#pragma unroll
    for (int a = 0; a < 4; a++)
#pragma unroll
        for (int b = 0; b < 4; b++)
#pragma unroll
            for (int c = 0; c < 4; c++) macc[a][b][c] = 0.0f;

    // ldmatrix lane addressing (verified correct in R5 pass)
    const uint32_t aOff = (uint32_t)((wm * 64 + (lane & 15)) * ROWB + (lane >> 4) * 16);
    const uint32_t bOff = (uint32_t)((wn * 32 + (((lane >> 4) << 3) | (lane & 7))) * ROWB
                                     + ((lane >> 3) & 1) * 16);

    auto load_stage = [&](int s, int kb) {
        const uint32_t sa = smA + s * A_STAGE_BYTES;
        const uint32_t sb = smB + s * B_STAGE_BYTES;
        const uint8_t* ga = gA + (size_t)kb * BK;
        const uint8_t* gb = gB + (size_t)kb * BK;
#pragma unroll
        for (int i = 0; i < 4; i++) {
            int cid = tid + i * 256;         // 0..1023 16B chunks
            int row = cid >> 3, col = cid & 7;
            CP_ASYNC_CG16(sa + row * ROWB + col * 16, ga + (size_t)row * K_DIM + col * 16);
            CP_ASYNC_CG16(sb + row * ROWB + col * 16, gb + (size_t)row * K_DIM + col * 16);
        }
    };

#pragma unroll
    for (int s = 0; s < STAGES - 1; s++) {
        load_stage(s, s);
        CP_COMMIT();
    }

    for (int kb = 0; kb < KTOT; kb++) {
        const float sb32 = __ldg(wsrow + kb) * 32.0f;   // fold back the /32 prescale

        CP_WAIT(STAGES - 2);
        __syncthreads();

        int nk = kb + (STAGES - 1);
        if (nk < KTOT) load_stage(nk % STAGES, nk);
        CP_COMMIT();

        const int st = kb % STAGES;
        const uint32_t sa = smA + st * A_STAGE_BYTES + aOff;
        const uint32_t sb = smB + st * B_STAGE_BYTES + bOff;

        uint32_t hacc[4][4][2];
#pragma unroll
        for (int mt = 0; mt < 4; mt++)
#pragma unroll
            for (int nt = 0; nt < 4; nt++) { hacc[mt][nt][0] = 0u; hacc[mt][nt][1] = 0u; }

#pragma unroll
        for (int ks = 0; ks < 4; ks++) {          // 4 x k32 within 128-k block
            uint32_t af[4][4];
            uint32_t bf[2][4];
#pragma unroll
            for (int mt = 0; mt < 4; mt++) LDSM_X4(af[mt], sa + mt * 16 * ROWB + ks * 32);
#pragma unroll
            for (int ng = 0; ng < 2; ng++) LDSM_X4(bf[ng], sb + ng * 16 * ROWB + ks * 32);
#pragma unroll
            for (int mt = 0; mt < 4; mt++) {
#pragma unroll
                for (int nt = 0; nt < 4; nt++) {
                    const int ng = nt >> 1, h = nt & 1;
                    MMA_FP8_H(hacc[mt][nt], af[mt], bf[ng][h * 2], bf[ng][h * 2 + 1]);
                }
            }
        }
        // promote f16 block accumulators into f32 master with weight scale
#pragma unroll
        for (int mt = 0; mt < 4; mt++) {
#pragma unroll
            for (int nt = 0; nt < 4; nt++) {
                float2 f0 = __half22float2(*reinterpret_cast<__half2*>(&hacc[mt][nt][0]));
                float2 f1 = __half22float2(*reinterpret_cast<__half2*>(&hacc[mt][nt][1]));
                macc[mt][nt][0] = fmaf(f0.x, sb32, macc[mt][nt][0]);
                macc[mt][nt][1] = fmaf(f0.y, sb32, macc[mt][nt][1]);
                macc[mt][nt][2] = fmaf(f1.x, sb32, macc[mt][nt][2]);
                macc[mt][nt][3] = fmaf(f1.y, sb32, macc[mt][nt][3]);
            }
        }
    }

    // epilogue: scale by per-token x_scale, store f32
    const int rowbase = mtile * BM + wm * 64 + (lane >> 2);
    const int colbase = ntile * BN + wn * 32 + (lane & 3) * 2;
#pragma unroll
    for (int mt = 0; mt < 4; mt++) {
        const int r0 = rowbase + mt * 16;
        const float s0 = xs[r0];
        const float s1 = xs[r0 + 8];
        float* o0 = out + (size_t)r0 * O_DIM + colbase;
        float* o1 = o0 + (size_t)8 * O_DIM;
#pragma unroll
        for (int nt = 0; nt < 4; nt++) {
            float2 v0 = make_float2(macc[mt][nt][0] * s0, macc[mt][nt][1] * s0);
            float2 v1 = make_float2(macc[mt][nt][2] * s1, macc[mt][nt][3] * s1);
            *reinterpret_cast<float2*>(o0 + nt * 8) = v0;
            *reinterpret_cast<float2*>(o1 + nt * 8) = v1;
        }
    }
}

// ---------------- Launch ----------------
extern "C" void kernel_launch(void* const* d_in, const int* in_sizes, int n_in,
                              void* d_out, int out_size)
{
    const float* x  = (const float*)d_in[0];
    const float* w  = (const float*)d_in[1];
    const float* ws = (const float*)d_in[2];
    float* out = (float*)d_out;

    const int K = K_DIM;
    const int T = in_sizes[0] / K;   // 8192
    const int O = in_sizes[1] / K;   // 4096

    void *pxq = nullptr, *pwq = nullptr, *pxs = nullptr;
    cudaGetSymbolAddress(&pxq, g_xq);
    cudaGetSymbolAddress(&pwq, g_wq);
    cudaGetSymbolAddress(&pxs, g_xs);

    quant_x_kernel<<<T, 256>>>(x, (uint8_t*)pxq, (float*)pxs);
    pack_w_kernel<<<(int)(((size_t)O * K / 4) / 256), 256>>>(w, (uint8_t*)pwq);

    cudaFuncSetAttribute(gemm_kernel, cudaFuncAttributeMaxDynamicSharedMemorySize, SMEM_BYTES);

    const int ntiles_n = O / BN;                 // 32
    const int grid = (T / BM) * ntiles_n;        // 2048
    gemm_kernel<<<grid, 256, SMEM_BYTES>>>(out, (float*)pxs, ws,
                                           (const uint8_t*)pxq, (const uint8_t*)pwq, ntiles_n);
}

// round 9
// speedup vs baseline: 1.0894x; 1.0894x over previous
#include <cuda_runtime.h>
#include <cuda_fp16.h>
#include <cuda_fp8.h>
#include <cstdint>
#include <cstddef>
#include <dlfcn.h>

// ---------------- Problem constants (fixed-shape bench) ----------------
#define T_MAX   8192
#define K_DIM   4096
#define O_DIM   4096
#define FP8_MAX 448.0f

// ---------------- Fallback GEMM tiling (R3 config, proven 905us) ----------------
#define BM 128
#define BN 128
#define BK 32
#define STAGES 4
#define KTOT   (K_DIM / BK)      // 128
#define PAD    8
#define LDROW  (BK + PAD)        // 40 halfs = 80 B
#define A_STAGE_BYTES (BM * LDROW * 2)   // 10240
#define B_STAGE_BYTES (BN * LDROW * 2)   // 10240
#define SMEM_BYTES    (STAGES * (A_STAGE_BYTES + B_STAGE_BYTES))   // 81920

// ---------------- Scratch (static device globals; no allocation) ----------------
__device__ __align__(1024) __half g_xq[(size_t)T_MAX * K_DIM];   // 64 MB fp16 (exact e4m3 vals)
__device__ __align__(1024) __half g_wd[(size_t)O_DIM * K_DIM];   // 32 MB fp16 (w * ws)
__device__ __align__(256)  uint8_t g_ws[32u * 1024u * 1024u];    // 32 MB cublasLt workspace
__device__ float g_xs[T_MAX];

// ---------------- PTX helpers (base ISA only) ----------------
__device__ __forceinline__ uint32_t smem_u32(const void* p) {
    uint32_t a;
    asm("{ .reg .u64 t; cvta.to.shared.u64 t, %1; cvt.u32.u64 %0, t; }" : "=r"(a) : "l"(p));
    return a;
}

#define CP_ASYNC_CG16(saddr, gptr) \
    asm volatile("cp.async.cg.shared.global [%0], [%1], 16;" :: "r"(saddr), "l"(gptr) : "memory")
#define CP_COMMIT() asm volatile("cp.async.commit_group;" ::: "memory")
#define CP_WAIT(n)  asm volatile("cp.async.wait_group %0;" :: "n"(n) : "memory")

#define LDSM_X4(r, addr) \
    asm volatile("ldmatrix.sync.aligned.m8n8.x4.shared.b16 {%0,%1,%2,%3}, [%4];" \
        : "=r"((r)[0]), "=r"((r)[1]), "=r"((r)[2]), "=r"((r)[3]) : "r"(addr))

#define MMA16816(d, a, b0, b1) \
    asm volatile("mma.sync.aligned.m16n8k16.row.col.f32.f16.f16.f32 " \
        "{%0,%1,%2,%3}, {%4,%5,%6,%7}, {%8,%9}, {%0,%1,%2,%3};" \
        : "+f"((d)[0]), "+f"((d)[1]), "+f"((d)[2]), "+f"((d)[3]) \
        : "r"((a)[0]), "r"((a)[1]), "r"((a)[2]), "r"((a)[3]), "r"(b0), "r"(b1))

// ---------------- Kernel 1: per-token amax + e4m3 round-trip -> fp16 ----------------
__device__ __forceinline__ __half2 fp8_roundtrip_h2(float a, float b) {
    float2 f2 = make_float2(a, b);
    __nv_fp8x2_storage_t p = __nv_cvt_float2_to_fp8x2(f2, __NV_SATFINITE, __NV_E4M3);
    __half2_raw hr = __nv_cvt_fp8x2_to_halfraw2(p, __NV_E4M3);
    return *reinterpret_cast<__half2*>(&hr);
}

__global__ void __launch_bounds__(256) quant_x_kernel(
    const float* __restrict__ x, __half* __restrict__ xq, float* __restrict__ xs)
{
    int row = blockIdx.x;
    int tid = threadIdx.x;
    const float4* xr = reinterpret_cast<const float4*>(x + (size_t)row * K_DIM);
    float4 v[4];
    float am = 0.0f;
#pragma unroll
    for (int j = 0; j < 4; j++) {
        v[j] = xr[tid + j * 256];
        am = fmaxf(am, fmaxf(fmaxf(fabsf(v[j].x), fabsf(v[j].y)),
                             fmaxf(fabsf(v[j].z), fabsf(v[j].w))));
    }
#pragma unroll
    for (int o = 16; o > 0; o >>= 1)
        am = fmaxf(am, __shfl_xor_sync(0xffffffffu, am, o));
    __shared__ float red[8];
    if ((tid & 31) == 0) red[tid >> 5] = am;
    __syncthreads();
    float m = red[0];
#pragma unroll
    for (int i = 1; i < 8; i++) m = fmaxf(m, red[i]);
    m = fmaxf(m, 1e-12f);
    float scale = m / FP8_MAX;
    if (tid == 0) xs[row] = scale;
    float rs = 1.0f / scale;
    __half2* outp = reinterpret_cast<__half2*>(xq + (size_t)row * K_DIM);
#pragma unroll
    for (int j = 0; j < 4; j++) {
        int f = tid + j * 256;
        outp[2 * f + 0] = fp8_roundtrip_h2(v[j].x * rs, v[j].y * rs);
        outp[2 * f + 1] = fp8_roundtrip_h2(v[j].z * rs, v[j].w * rs);
    }
}

// ---------------- Kernel 2: blockwise weight dequant -> fp16 ----------------
__global__ void __launch_bounds__(256) dequant_w_kernel(
    const float* __restrict__ w, const float* __restrict__ ws, __half* __restrict__ wd)
{
    size_t idx = ((size_t)blockIdx.x * blockDim.x + threadIdx.x) * 4;
    int o = (int)(idx >> 12);
    int i = (int)(idx & 4095);
    float s = ws[(o >> 7) * (K_DIM / 128) + (i >> 7)];
    float4 v = *reinterpret_cast<const float4*>(w + idx);
    __half2 h0 = __floats2half2_rn(v.x * s, v.y * s);
    __half2 h1 = __floats2half2_rn(v.z * s, v.w * s);
    __half2* p = reinterpret_cast<__half2*>(wd + idx);
    p[0] = h0;
    p[1] = h1;
}

// ---------------- Kernel: per-row scale of GEMM output ----------------
__global__ void __launch_bounds__(256) scale_rows_kernel(
    float* __restrict__ out, const float* __restrict__ xs)
{
    int row = blockIdx.x;
    float s = xs[row];
    float4* p = reinterpret_cast<float4*>(out + (size_t)row * O_DIM);
#pragma unroll
    for (int j = 0; j < 4; j++) {
        int i = threadIdx.x + j * 256;
        float4 v = p[i];
        v.x *= s; v.y *= s; v.z *= s; v.w *= s;
        p[i] = v;
    }
}

// ---------------- Fallback GEMM (R3, proven): f16 mma.sync 128x128x32 ----------------
__global__ void __launch_bounds__(256, 2) gemm_fallback(
    float* __restrict__ out, const float* __restrict__ xs,
    const __half* __restrict__ A, const __half* __restrict__ B, int ntiles_n)
{
    extern __shared__ char smem[];
    const uint32_t smA = smem_u32(smem);
    const uint32_t smB = smA + STAGES * A_STAGE_BYTES;

    const int tid  = threadIdx.x;
    const int lane = tid & 31;
    const int wid  = tid >> 5;
    const int wm   = wid & 1;
    const int wn   = wid >> 1;

    const int ntile = blockIdx.x % ntiles_n;
    const int mtile = blockIdx.x / ntiles_n;

    const __half* gA = A + (size_t)(mtile * BM) * K_DIM;
    const __half* gB = B + (size_t)(ntile * BN) * K_DIM;

    const int lrow = tid >> 2;
    const int lcc  = tid & 3;

    float acc[4][4][4];
#pragma unroll
    for (int a = 0; a < 4; a++)
#pragma unroll
        for (int b = 0; b < 4; b++)
#pragma unroll
            for (int c = 0; c < 4; c++) acc[a][b][c] = 0.0f;

    const uint32_t aBase = smA + (uint32_t)(((wm * 64 + (lane & 15)) * LDROW + (lane >> 4) * 8) * 2);
    const uint32_t bBase = smB + (uint32_t)(((wn * 32 + (lane & 15)) * LDROW + (lane >> 4) * 8) * 2);

    auto load_stage = [&](int s, int kt) {
        const uint32_t sa = smA + s * A_STAGE_BYTES;
        const uint32_t sb = smB + s * B_STAGE_BYTES;
        const __half* ga = gA + kt * BK;
        const __half* gb = gB + kt * BK;
#pragma unroll
        for (int i = 0; i < 2; i++) {
            int row = lrow + i * 64;
            uint32_t so = (uint32_t)(row * (LDROW * 2) + lcc * 16);
            CP_ASYNC_CG16(sa + so, ga + (size_t)row * K_DIM + lcc * 8);
            CP_ASYNC_CG16(sb + so, gb + (size_t)row * K_DIM + lcc * 8);
        }
    };

#pragma unroll
    for (int s = 0; s < STAGES - 1; s++) {
        load_stage(s, s);
        CP_COMMIT();
    }

    for (int kt = 0; kt < KTOT; kt++) {
        CP_WAIT(2);
        __syncthreads();

        int nk = kt + (STAGES - 1);
        if (nk < KTOT) load_stage((nk & (STAGES - 1)), nk);
        CP_COMMIT();

        const int s = kt & (STAGES - 1);
        const uint32_t sa = aBase + s * A_STAGE_BYTES;
        const uint32_t sb = bBase + s * B_STAGE_BYTES;
#pragma unroll
        for (int ks = 0; ks < 2; ks++) {
            const uint32_t ka = sa + ks * 32;
            const uint32_t kb = sb + ks * 32;
            uint32_t af[4][4];
            uint32_t bf[2][4];
#pragma unroll
            for (int mt = 0; mt < 4; mt++) LDSM_X4(af[mt], ka + mt * 16 * (LDROW * 2));
#pragma unroll
            for (int pt = 0; pt < 2; pt++) LDSM_X4(bf[pt], kb + pt * 16 * (LDROW * 2));
#pragma unroll
            for (int mt = 0; mt < 4; mt++) {
#pragma unroll
                for (int nt = 0; nt < 4; nt++) {
                    const int pt = nt >> 1, od = nt & 1;
                    MMA16816(acc[mt][nt], af[mt], bf[pt][od], bf[pt][od + 2]);
                }
            }
        }
    }

    const int rowbase = mtile * BM + wm * 64 + (lane >> 2);
    const int colbase = ntile * BN + wn * 32 + (lane & 3) * 2;
#pragma unroll
    for (int mt = 0; mt < 4; mt++) {
        const int r0 = rowbase + mt * 16;
        const float s0 = xs[r0];
        const float s1 = xs[r0 + 8];
        float* o0 = out + (size_t)r0 * O_DIM + colbase;
        float* o1 = o0 + (size_t)8 * O_DIM;
#pragma unroll
        for (int nt = 0; nt < 4; nt++) {
            float2 v0 = make_float2(acc[mt][nt][0] * s0, acc[mt][nt][1] * s0);
            float2 v1 = make_float2(acc[mt][nt][2] * s1, acc[mt][nt][3] * s1);
            *reinterpret_cast<float2*>(o0 + nt * 8) = v0;
            *reinterpret_cast<float2*>(o1 + nt * 8) = v1;
        }
    }
}

// ---------------- cublasLt ABI (hand-declared; loaded via dlopen) ----------------
struct LtAlgo { uint64_t data[8]; };
struct LtHeurResult {
    LtAlgo algo;
    size_t workspaceSize;
    int    state;
    float  wavesCount;
    int    reserved[4];
};

typedef int (*fn_ltCreate)(void**);
typedef int (*fn_descCreate)(void**, int /*computeType*/, int /*scaleType*/);
typedef int (*fn_descSet)(void*, int, const void*, size_t);
typedef int (*fn_layoutCreate)(void**, int /*dtype*/, uint64_t, uint64_t, int64_t);
typedef int (*fn_prefCreate)(void**);
typedef int (*fn_prefSet)(void*, int, const void*, size_t);
typedef int (*fn_heur)(void*, void*, void*, void*, void*, void*, void*, int, LtHeurResult*, int*);
typedef int (*fn_matmul)(void*, void*, const void*, const void*, void*, const void*, void*,
                         const void*, const void*, void*, void*, void*, const void*,
                         void*, size_t, cudaStream_t);

static bool try_cublaslt(const __half* wd, const __half* xq, float* out, void* wsptr) {
    void* lib = dlopen("libcublasLt.so.13", RTLD_NOW | RTLD_GLOBAL);
    if (!lib) lib = dlopen("libcublasLt.so.12", RTLD_NOW | RTLD_GLOBAL);
    if (!lib) lib = dlopen("libcublasLt.so", RTLD_NOW | RTLD_GLOBAL);
    if (!lib) return false;

    fn_ltCreate     pCreate  = (fn_ltCreate)    dlsym(lib, "cublasLtCreate");
    fn_descCreate   pDesc    = (fn_descCreate)  dlsym(lib, "cublasLtMatmulDescCreate");
    fn_descSet      pDescSet = (fn_descSet)     dlsym(lib, "cublasLtMatmulDescSetAttribute");
    fn_layoutCreate pLayout  = (fn_layoutCreate)dlsym(lib, "cublasLtMatrixLayoutCreate");
    fn_prefCreate   pPref    = (fn_prefCreate)  dlsym(lib, "cublasLtMatmulPreferenceCreate");
    fn_prefSet      pPrefSet = (fn_prefSet)     dlsym(lib, "cublasLtMatmulPreferenceSetAttribute");
    fn_heur         pHeur    = (fn_heur)        dlsym(lib, "cublasLtMatmulAlgoGetHeuristic");
    fn_matmul       pMatmul  = (fn_matmul)      dlsym(lib, "cublasLtMatmul");
    if (!pCreate || !pDesc || !pDescSet || !pLayout || !pPref || !pPrefSet || !pHeur || !pMatmul)
        return false;

    void* handle = nullptr;
    if (pCreate(&handle) != 0 || !handle) return false;

    // computeType=CUBLAS_COMPUTE_32F(68), scaleType=CUDA_R_32F(0)
    void* op = nullptr;
    if (pDesc(&op, 68, 0) != 0 || !op) return false;
    int opT = 1, opN = 0;   // CUBLAS_OP_T / CUBLAS_OP_N
    if (pDescSet(op, 3 /*TRANSA*/, &opT, sizeof(int)) != 0) return false;
    if (pDescSet(op, 4 /*TRANSB*/, &opN, sizeof(int)) != 0) return false;

    // A = wd: stored [K_DIM x O_DIM] col-major (== row-major [O,K]), ld=K; op(A)=A^T -> [O,K]
    // B = xq: stored [K_DIM x T_MAX] col-major (== row-major [T,K]), ld=K; op(B)=B   -> [K,T]
    // D = out: [O_DIM x T_MAX] col-major, ld=O (== row-major [T,O])
    void *la = nullptr, *lb = nullptr, *lc = nullptr;
    if (pLayout(&la, 2 /*R_16F*/, K_DIM, O_DIM, K_DIM) != 0 || !la) return false;
    if (pLayout(&lb, 2 /*R_16F*/, K_DIM, T_MAX, K_DIM) != 0 || !lb) return false;
    if (pLayout(&lc, 0 /*R_32F*/, O_DIM, T_MAX, O_DIM) != 0 || !lc) return false;

    void* pref = nullptr;
    if (pPref(&pref) != 0 || !pref) return false;
    size_t wssz = sizeof(g_ws);
    if (pPrefSet(pref, 1 /*MAX_WORKSPACE_BYTES*/, &wssz, sizeof(size_t)) != 0) return false;

    LtHeurResult res[4];
    int nres = 0;
    if (pHeur(handle, op, la, lb, lc, lc, pref, 4, res, &nres) != 0 || nres < 1) return false;
    if (res[0].state != 0) return false;

    float alpha = 1.0f, beta = 0.0f;
    if (pMatmul(handle, op, &alpha, wd, la, xq, lb, &beta, out, lc, out, lc,
                &res[0].algo, wsptr, wssz, (cudaStream_t)0) != 0)
        return false;
    return true;
}

// ---------------- Launch ----------------
extern "C" void kernel_launch(void* const* d_in, const int* in_sizes, int n_in,
                              void* d_out, int out_size)
{
    const float* x  = (const float*)d_in[0];
    const float* w  = (const float*)d_in[1];
    const float* ws = (const float*)d_in[2];
    float* out = (float*)d_out;

    const int K = K_DIM;
    const int T = in_sizes[0] / K;   // 8192
    const int O = in_sizes[1] / K;   // 4096

    void *pxq = nullptr, *pwd = nullptr, *pxs = nullptr, *pws = nullptr;
    cudaGetSymbolAddress(&pxq, g_xq);
    cudaGetSymbolAddress(&pwd, g_wd);
    cudaGetSymbolAddress(&pxs, g_xs);
    cudaGetSymbolAddress(&pws, g_ws);

    quant_x_kernel<<<T, 256>>>(x, (__half*)pxq, (float*)pxs);
    dequant_w_kernel<<<(int)(((size_t)O * K / 4) / 256), 256>>>(w, ws, (__half*)pwd);

    if (try_cublaslt((const __half*)pwd, (const __half*)pxq, out, pws)) {
        scale_rows_kernel<<<T, 256>>>(out, (float*)pxs);
    } else {
        cudaFuncSetAttribute(gemm_fallback, cudaFuncAttributeMaxDynamicSharedMemorySize, SMEM_BYTES);
        const int ntiles_n = O / BN;                 // 32
        const int grid = (T / BM) * ntiles_n;        // 2048
        gemm_fallback<<<grid, 256, SMEM_BYTES>>>(out, (float*)pxs,
                                                 (const __half*)pxq, (const __half*)pwd, ntiles_n);
    }
}